// round 3
// baseline (speedup 1.0000x reference)
#include <cuda_runtime.h>
#include <math.h>
#include <stdint.h>

// ---------------- problem constants ----------------
#define T_DIM 256
#define B_DIM 256
#define D_DIM 128
#define H_DIM 512
#define G3H   1536            // 3*H
#define TM1   255             // T-1
#define K10D  1280            // 10*D
#define PRE_ROWS (B_DIM*TM1)  // 65280
#define PRED_ELEMS (PRE_ROWS*D_DIM)  // 8355840

// persistent GRU geometry
#define NCTA   128            // 32 unit-chunks x 4 batch-groups
#define GTPB   256
#define UPC    16             // units per CTA
#define BPC    64             // batches per CTA
#define CHUNK  64             // k per smem chunk
#define NCHUNK (H_DIM/CHUNK)  // 8
#define GRU_SMEM ((H_DIM*48 + 2*CHUNK*BPC)*4)   // 131072 B

// ---------------- scratch (static device arrays; no cudaMalloc allowed) ------
__device__ float g_xwT[(size_t)T_DIM * G3H * B_DIM];      // [t][col][b]
__device__ float g_hidden[(size_t)T_DIM * B_DIM * H_DIM]; // [t][b][H]
__device__ float g_pre[(size_t)PRE_ROWS * K10D];          // (b,t) major rows
__device__ float g_td[PRE_ROWS];
__device__ float g_hT[2 * H_DIM * B_DIM];                 // [buf][k][b]
__device__ unsigned g_bar[260];                           // grid barrier counters

// ---------------- f32x2 helpers ----------------
typedef unsigned long long ull;
__device__ __forceinline__ ull lds64(unsigned a) {
    ull v; asm("ld.shared.b64 %0, [%1];" : "=l"(v) : "r"(a)); return v;
}
__device__ __forceinline__ ull swap64(ull p) {
    unsigned lo, hi;
    asm("mov.b64 {%0,%1}, %2;" : "=r"(lo), "=r"(hi) : "l"(p));
    ull q; asm("mov.b64 %0, {%1,%2};" : "=l"(q) : "r"(hi), "r"(lo)); return q;
}
__device__ __forceinline__ void fma2(ull& acc, ull a, ull b) {
    asm("fma.rn.f32x2 %0, %1, %2, %0;" : "+l"(acc) : "l"(a), "l"(b));
}
__device__ __forceinline__ void unpack2(ull p, float& lo, float& hi) {
    asm("mov.b64 {%0,%1}, %2;" : "=f"(lo), "=f"(hi) : "l"(p));
}
__device__ __forceinline__ ull pack2(float lo, float hi) {
    ull p; asm("mov.b64 %0, {%1,%2};" : "=l"(p) : "f"(lo), "f"(hi)); return p;
}
__device__ __forceinline__ float fsigmoid(float x) {
    return __fdividef(1.f, 1.f + __expf(-x));
}
__device__ __forceinline__ float ftanh(float x) {
    return 1.f - __fdividef(2.f, __expf(2.f * x) + 1.f);
}

// =======================================================================
// Generic 128x128 fp32 GEMM (f32x2 inner loop), C = A[M,K]*B[N,K]^T (+epi)
// MODE 0: xw  -> stores TRANSPOSED into xwT[t][col][b], c += bias
// MODE 1: pre -> A rows remapped into hidden[t][b][H] (skip t=255);
//                c = sigmoid(c + td[row]*w1last[col*513] + bias)
// MODE 2: preds -> c = (t < lengths[b]-1) ? c+bias : 0
// =======================================================================
template <int MODE>
__global__ __launch_bounds__(256)
void gemm128(const float* __restrict__ A, const float* __restrict__ B,
             float* __restrict__ C,
             int M, int N, int K, int lda, int ldb, int ldc,
             const float* __restrict__ bias,
             const float* __restrict__ td,
             const float* __restrict__ w1last,
             const int* __restrict__ lengths)
{
    __shared__ __align__(16) ull   As2[8][128];   // A values pre-duplicated (a,a)
    __shared__ __align__(16) float Bs[8][128];

    const int tid = threadIdx.x;
    const int row0 = blockIdx.y * 128;
    const int col0 = blockIdx.x * 128;
    const int tx = tid & 15;       // cols tx*8 .. tx*8+7
    const int ty = tid >> 4;       // rows ty*8 .. ty*8+7

    int lr[4], lk[4];
    size_t aoff[4], boff[4];
#pragma unroll
    for (int i = 0; i < 4; i++) {
        int lin = tid + i * 256;
        lr[i] = lin >> 3;
        lk[i] = lin & 7;
        int grow = row0 + lr[i];
        int arow = grow;
        if (MODE == 1) {               // row=(b,t) t<255 -> hidden[t][b]
            int b_ = grow / 255;
            int t_ = grow - b_ * 255;
            arow = t_ * 256 + b_;
        }
        aoff[i] = (size_t)arow * lda + lk[i];
        boff[i] = (size_t)(col0 + lr[i]) * ldb + lk[i];
    }

    ull acc2[8][4];
#pragma unroll
    for (int i = 0; i < 8; i++)
#pragma unroll
        for (int j = 0; j < 4; j++) acc2[i][j] = 0ull;

    for (int k0 = 0; k0 < K; k0 += 8) {
#pragma unroll
        for (int i = 0; i < 4; i++) {
            int gk = k0 + lk[i];
            float av = (gk < K) ? A[aoff[i] + k0] : 0.f;
            As2[lk[i]][lr[i]] = pack2(av, av);
            Bs[lk[i]][lr[i]] = (gk < K) ? B[boff[i] + k0] : 0.f;
        }
        __syncthreads();
#pragma unroll
        for (int kk = 0; kk < 8; kk++) {
            ull a2[8], b2[4];
            const ull* ap = &As2[kk][ty * 8];
            const ull* bp = (const ull*)&Bs[kk][tx * 8];
#pragma unroll
            for (int i = 0; i < 8; i++) a2[i] = ap[i];
#pragma unroll
            for (int j = 0; j < 4; j++) b2[j] = bp[j];
#pragma unroll
            for (int i = 0; i < 8; i++)
#pragma unroll
                for (int j = 0; j < 4; j++) fma2(acc2[i][j], a2[i], b2[j]);
        }
        __syncthreads();
    }

    // unpack to scalar tile
    float acc[8][8];
#pragma unroll
    for (int i = 0; i < 8; i++)
#pragma unroll
        for (int j = 0; j < 4; j++)
            unpack2(acc2[i][j], acc[i][2 * j], acc[i][2 * j + 1]);

    if (MODE == 0) {
        // transposed store: C[t][col][b], 128-row tile = fixed t, b range
        int tt = row0 >> 8;
        int b0 = (row0 & 255) + ty * 8;
#pragma unroll
        for (int j = 0; j < 8; j++) {
            int gcol = col0 + tx * 8 + j;
            float bz = bias[gcol];
            float4 v0 = make_float4(acc[0][j] + bz, acc[1][j] + bz,
                                    acc[2][j] + bz, acc[3][j] + bz);
            float4 v1 = make_float4(acc[4][j] + bz, acc[5][j] + bz,
                                    acc[6][j] + bz, acc[7][j] + bz);
            size_t base = ((size_t)tt * G3H + gcol) * B_DIM + b0;
            *(float4*)(C + base) = v0;
            *(float4*)(C + base + 4) = v1;
        }
        return;
    }

#pragma unroll
    for (int i = 0; i < 8; i++) {
        int grow = row0 + ty * 8 + i;
        float tdv = 0.f;
        int b_ = 0, t_ = 0;
        if (MODE == 1) tdv = td[grow];
        if (MODE == 2) { b_ = grow / 255; t_ = grow - b_ * 255; }
#pragma unroll
        for (int j = 0; j < 8; j++) {
            int gcol = col0 + tx * 8 + j;
            float v = acc[i][j];
            if (MODE == 1) {
                v += bias[gcol] + tdv * w1last[(size_t)gcol * 513];
                v = 1.f / (1.f + expf(-v));
            } else { // MODE 2
                v = (t_ < lengths[b_] - 1) ? (v + bias[gcol]) : 0.f;
            }
            C[(size_t)grow * ldc + gcol] = v;
        }
    }
}

// =======================================================================
// Persistent GRU: 128 CTAs resident (1/SM), all 256 steps in one launch.
// =======================================================================
__global__ __launch_bounds__(GTPB, 1)
void gru_persistent(const float* __restrict__ h0,
                    const float* __restrict__ xwT,
                    const float* __restrict__ w_hh,
                    const float* __restrict__ b_hh,
                    const int*   __restrict__ lengths,
                    float* __restrict__ hT,
                    float* __restrict__ hidden,
                    unsigned* __restrict__ bar)
{
    extern __shared__ float sm[];
    float* w_s = sm;                       // [512][48]
    float* h_s = sm + H_DIM * 48;          // [2][64][64]

    const int tid = threadIdx.x;
    const int jc  = blockIdx.x & 31;
    const int bgi = blockIdx.x >> 5;
    const int ubase = jc * UPC;
    const int bbase = bgi * BPC;
    const int ut = tid >> 5;               // 0..7
    const int bt = tid & 31;               // 0..31
    const int u0 = ut * 2;
    const int b0 = bt * 2;

    unsigned sm_base;
    asm("{.reg .u64 t0; cvta.to.shared.u64 t0, %1; cvt.u32.u64 %0, t0;}"
        : "=r"(sm_base) : "l"(sm));
    const unsigned sw_w = sm_base;
    const unsigned sw_h = sm_base + H_DIM * 48 * 4;

    // ---- one-time: load w slice (48 rows x 512) transposed into w_s[k][row]
    for (int i = tid; i < 48 * 128; i += GTPB) {
        int r = i >> 7, kq = i & 127;
        int g = r >> 4, u = r & 15;
        float4 w4 = *(const float4*)(w_hh + (size_t)(g * H_DIM + ubase + u) * H_DIM + kq * 4);
        int col = g * 16 + u;
        w_s[(kq * 4 + 0) * 48 + col] = w4.x;
        w_s[(kq * 4 + 1) * 48 + col] = w4.y;
        w_s[(kq * 4 + 2) * 48 + col] = w4.z;
        w_s[(kq * 4 + 3) * 48 + col] = w4.w;
    }
    // ---- one-time: transpose own tile of h0 into hT[0]
    for (int i = tid; i < UPC * BPC; i += GTPB) {
        int u = i >> 6, b = i & 63;
        hT[(size_t)(ubase + u) * B_DIM + bbase + b] =
            h0[(size_t)(bbase + b) * H_DIM + ubase + u];
    }
    // grid barrier 0
    __syncthreads();
    if (tid == 0) {
        __threadfence();
        atomicAdd(&bar[0], 1u);
        volatile unsigned* f = &bar[0];
        while (*f < (unsigned)NCTA) __nanosleep(64);
    }
    __syncthreads();

    float bh[3][2];
#pragma unroll
    for (int g = 0; g < 3; g++) {
        bh[g][0] = b_hh[g * H_DIM + ubase + u0];
        bh[g][1] = b_hh[g * H_DIM + ubase + u0 + 1];
    }
    const int len0 = lengths[bbase + b0];
    const int len1 = lengths[bbase + b0 + 1];

    const unsigned hoff = b0 * 4;
    const unsigned woff = u0 * 4;

    for (int t = 0; t < T_DIM; t++) {
        const float* hcur = hT + (size_t)(t & 1) * H_DIM * B_DIM;
        float*       hnxt = hT + (size_t)((t + 1) & 1) * H_DIM * B_DIM;

        ull accd0 = 0, accd1 = 0, accd2 = 0;
        ull accc0 = 0, accc1 = 0, accc2 = 0;

        float4 pf[4];
#pragma unroll
        for (int i = 0; i < 4; i++) {
            int q = tid + i * GTPB;
            int k = q >> 4, bq = q & 15;
            pf[i] = __ldcg((const float4*)(hcur + (size_t)k * B_DIM + bbase + bq * 4));
        }

        for (int c = 0; c < NCHUNK; c++) {
            __syncthreads();
#pragma unroll
            for (int i = 0; i < 4; i++) {
                int q = tid + i * GTPB;
                int k = q >> 4, bq = q & 15;
                *(float4*)(h_s + (c & 1) * (CHUNK * BPC) + k * BPC + bq * 4) = pf[i];
            }
            if (c < NCHUNK - 1) {
#pragma unroll
                for (int i = 0; i < 4; i++) {
                    int q = tid + i * GTPB;
                    int k = q >> 4, bq = q & 15;
                    pf[i] = __ldcg((const float4*)(hcur + (size_t)((c + 1) * CHUNK + k) * B_DIM + bbase + bq * 4));
                }
            }
            __syncthreads();

            const unsigned hbase = sw_h + (c & 1) * (CHUNK * BPC * 4) + hoff;
            const unsigned wbase = sw_w + (c * CHUNK) * 192 + woff;
#pragma unroll 32
            for (int kk = 0; kk < CHUNK; kk++) {
                ull h2  = lds64(hbase + kk * 256);
                ull h2s = swap64(h2);
                ull w0  = lds64(wbase + kk * 192);
                ull w1  = lds64(wbase + kk * 192 + 64);
                ull w2  = lds64(wbase + kk * 192 + 128);
                fma2(accd0, w0, h2);  fma2(accc0, w0, h2s);
                fma2(accd1, w1, h2);  fma2(accc1, w1, h2s);
                fma2(accd2, w2, h2);  fma2(accc2, w2, h2s);
            }
        }

        float A0[4], A1[4], A2[4];
        unpack2(accd0, A0[0], A0[3]); unpack2(accc0, A0[1], A0[2]);
        unpack2(accd1, A1[0], A1[3]); unpack2(accc1, A1[1], A1[2]);
        unpack2(accd2, A2[0], A2[3]); unpack2(accc2, A2[1], A2[2]);

#pragma unroll
        for (int cb = 0; cb < 4; cb++) {
            const int du = cb >> 1, db = cb & 1;
            const int uu = ubase + u0 + du;
            const int bb = bbase + b0 + db;
            const size_t xbase = ((size_t)t * G3H + uu) * B_DIM + bb;
            float xr = __ldg(xwT + xbase);
            float xz = __ldg(xwT + xbase + (size_t)H_DIM * B_DIM);
            float xn = __ldg(xwT + xbase + (size_t)2 * H_DIM * B_DIM);
            float hold = __ldcg(hcur + (size_t)uu * B_DIM + bb);
            float r = fsigmoid(xr + A0[cb] + bh[0][du]);
            float z = fsigmoid(xz + A1[cb] + bh[1][du]);
            float n = ftanh(xn + r * (A2[cb] + bh[2][du]));
            float hnew = (1.f - z) * n + z * hold;
            bool valid = t < ((db == 0) ? len0 : len1);
            hnxt[(size_t)uu * B_DIM + bb] = valid ? hnew : hold;
            hidden[((size_t)t * B_DIM + bb) * H_DIM + uu] = valid ? hnew : 0.f;
        }

        __syncthreads();
        if (tid == 0) {
            __threadfence();
            atomicAdd(&bar[t + 1], 1u);
            volatile unsigned* f = &bar[t + 1];
            while (*f < (unsigned)NCTA) __nanosleep(64);
        }
        __syncthreads();
    }
}

// =======================================================================
__global__ void td_kernel(const float* __restrict__ x, float* __restrict__ td)
{
    int i = blockIdx.x * 256 + threadIdx.x;
    if (i < PRE_ROWS) {
        int b = i / 255;
        int t = i - b * 255;
        td[i] = x[(size_t)((t + 1) * B_DIM + b) * (D_DIM + 1)]
              - x[(size_t)(t * B_DIM + b) * (D_DIM + 1)];
    }
}

// =======================================================================
__global__ void tail_kernel(const float* __restrict__ hT0,
                            const float* __restrict__ wp,
                            const float* __restrict__ bp,
                            const int* __restrict__ lengths,
                            float* __restrict__ out)
{
    int b = blockIdx.x;
    int w = threadIdx.x >> 5;
    int lane = threadIdx.x & 31;
    float s = 0.f;
    for (int k = lane; k < H_DIM; k += 32)
        s += hT0[(size_t)k * B_DIM + b] * wp[(size_t)w * H_DIM + k];
#pragma unroll
    for (int o = 16; o; o >>= 1) s += __shfl_xor_sync(0xffffffffu, s, o);
    if (lane == 0)
        out[PRED_ELEMS + b * 3 + w] = expf(-(s + bp[w]));
    if (threadIdx.x == 0)
        out[PRED_ELEMS + B_DIM * 3 + b] = (float)lengths[b];
}

// =======================================================================
extern "C" void kernel_launch(void* const* d_in, const int* in_sizes, int n_in,
                              void* d_out, int out_size)
{
    const float* x    = (const float*)d_in[0];
    const float* h0   = (const float*)d_in[1];
    const int*   lens = (const int*)  d_in[2];
    const float* w_ih = (const float*)d_in[3];
    const float* w_hh = (const float*)d_in[4];
    const float* b_ih = (const float*)d_in[5];
    const float* b_hh = (const float*)d_in[6];
    const float* w1   = (const float*)d_in[7];
    const float* b1   = (const float*)d_in[8];
    const float* w2   = (const float*)d_in[9];
    const float* b2   = (const float*)d_in[10];
    const float* wp   = (const float*)d_in[11];
    const float* bp   = (const float*)d_in[12];
    float* out = (float*)d_out;

    float *xwT, *hidden, *pre, *td, *hT;
    unsigned* bar;
    cudaGetSymbolAddress((void**)&xwT,    g_xwT);
    cudaGetSymbolAddress((void**)&hidden, g_hidden);
    cudaGetSymbolAddress((void**)&pre,    g_pre);
    cudaGetSymbolAddress((void**)&td,     g_td);
    cudaGetSymbolAddress((void**)&hT,     g_hT);
    cudaGetSymbolAddress((void**)&bar,    g_bar);

    cudaFuncSetAttribute(gru_persistent,
                         cudaFuncAttributeMaxDynamicSharedMemorySize, GRU_SMEM);

    cudaMemsetAsync(bar, 0, 260 * sizeof(unsigned));

    td_kernel<<<255, 256>>>(x, td);

    // xwT[t][col][b] = (x @ w_ih^T + b_ih) transposed
    gemm128<0><<<dim3(G3H / 128, (T_DIM * B_DIM) / 128), 256>>>(
        x, w_ih, xwT, T_DIM * B_DIM, G3H, D_DIM + 1,
        D_DIM + 1, D_DIM + 1, G3H, b_ih, nullptr, nullptr, nullptr);

    // persistent GRU (all 256 steps)
    gru_persistent<<<NCTA, GTPB, GRU_SMEM>>>(h0, xwT, w_hh, b_hh, lens,
                                             hT, hidden, bar);

    // pre = sigmoid(hwt[:, :-1] @ w1^T + b1), td column fused
    gemm128<1><<<dim3(K10D / 128, PRE_ROWS / 128), 256>>>(
        hidden, w1, pre, PRE_ROWS, K10D, H_DIM,
        H_DIM, H_DIM + 1, K10D, b1, td, w1 + H_DIM, nullptr);

    // preds = mask(pre @ w2^T + b2) -> d_out
    gemm128<2><<<dim3(1, PRE_ROWS / 128), 256>>>(
        pre, w2, out, PRE_ROWS, D_DIM, K10D,
        K10D, K10D, D_DIM, b2, nullptr, nullptr, lens);

    // dist_params + lengths (final h is hT buffer 0 after 256 steps)
    tail_kernel<<<B_DIM, 96>>>(hT, wp, bp, lens, out);
}

// round 4
// speedup vs baseline: 1.1308x; 1.1308x over previous
#include <cuda_runtime.h>
#include <math.h>
#include <stdint.h>

// ---------------- problem constants ----------------
#define T_DIM 256
#define B_DIM 256
#define D_DIM 128
#define H_DIM 512
#define G3H   1536            // 3*H
#define TM1   255             // T-1
#define K10D  1280            // 10*D
#define PRE_ROWS (B_DIM*TM1)  // 65280
#define PRED_ELEMS (PRE_ROWS*D_DIM)  // 8355840

// persistent GRU geometry
#define NCTA   128            // 32 unit-chunks x 4 batch-groups
#define GTPB   256
#define UPC    16             // units per CTA
#define BPC    64             // batches per CTA
#define CHUNK  64             // k per smem chunk
#define NCHUNK (H_DIM/CHUNK)  // 8
#define GRU_SMEM ((H_DIM*48 + 2*CHUNK*BPC)*4)   // 131072 B

// ---------------- scratch (static device arrays; no cudaMalloc allowed) ------
__device__ float g_xwT[(size_t)T_DIM * G3H * B_DIM];      // [t][col][b]
__device__ float g_hidden[(size_t)T_DIM * B_DIM * H_DIM]; // [t][b][H]
__device__ float g_pre[(size_t)PRE_ROWS * K10D];          // (b,t) major rows
__device__ float g_td[PRE_ROWS];
__device__ float g_hT[2 * H_DIM * B_DIM];                 // [buf][k][b]
__device__ unsigned g_bar[260];                           // grid barrier counters

// ---------------- f32x2 helpers ----------------
typedef unsigned long long ull;
__device__ __forceinline__ ull lds64(unsigned a) {
    ull v; asm("ld.shared.b64 %0, [%1];" : "=l"(v) : "r"(a)); return v;
}
__device__ __forceinline__ ull swap64(ull p) {
    unsigned lo, hi;
    asm("mov.b64 {%0,%1}, %2;" : "=r"(lo), "=r"(hi) : "l"(p));
    ull q; asm("mov.b64 %0, {%1,%2};" : "=l"(q) : "r"(hi), "r"(lo)); return q;
}
__device__ __forceinline__ void fma2(ull& acc, ull a, ull b) {
    asm("fma.rn.f32x2 %0, %1, %2, %0;" : "+l"(acc) : "l"(a), "l"(b));
}
__device__ __forceinline__ void unpack2(ull p, float& lo, float& hi) {
    asm("mov.b64 {%0,%1}, %2;" : "=f"(lo), "=f"(hi) : "l"(p));
}
__device__ __forceinline__ ull pack2(float lo, float hi) {
    ull p; asm("mov.b64 %0, {%1,%2};" : "=l"(p) : "f"(lo), "f"(hi)); return p;
}
__device__ __forceinline__ float fsigmoid(float x) {
    return __fdividef(1.f, 1.f + __expf(-x));
}
__device__ __forceinline__ float ftanh(float x) {
    return 1.f - __fdividef(2.f, __expf(2.f * x) + 1.f);
}

// =======================================================================
// Generic 128x128 fp32 GEMM (f32x2 inner loop, 2 CTA/SM), C = A*B^T (+epi)
// MODE 0: xw  -> stores TRANSPOSED into xwT[t][col][b], c += bias
// MODE 1: pre -> A rows remapped into hidden[t][b][H] (skip t=255);
//                c = sigmoid(c + td[row]*w1last[col*513] + bias)
// MODE 2: preds -> c = (t < lengths[b]-1) ? c+bias : 0
// =======================================================================
template <int MODE>
__global__ __launch_bounds__(256, 2)
void gemm128(const float* __restrict__ A, const float* __restrict__ B,
             float* __restrict__ C,
             int M, int N, int K, int lda, int ldb, int ldc,
             const float* __restrict__ bias,
             const float* __restrict__ td,
             const float* __restrict__ w1last,
             const int* __restrict__ lengths)
{
    __shared__ __align__(16) ull   As2[8][128];   // A values pre-duplicated (a,a)
    __shared__ __align__(16) float Bs[8][128];

    const int tid = threadIdx.x;
    const int row0 = blockIdx.y * 128;
    const int col0 = blockIdx.x * 128;
    const int tx = tid & 15;       // cols tx*8 .. tx*8+7
    const int ty = tid >> 4;       // rows ty*8 .. ty*8+7

    // 32-bit load offsets (all operand arrays < 2^31 elements)
    unsigned aoff[4], boff[4];
    int lk[4];
    int lrr[4];
#pragma unroll
    for (int i = 0; i < 4; i++) {
        int lin = tid + i * 256;
        int lr = lin >> 3;
        lk[i] = lin & 7;
        lrr[i] = lr;
        int grow = row0 + lr;
        int arow = grow;
        if (MODE == 1) {               // row=(b,t) t<255 -> hidden[t][b]
            int b_ = grow / 255;
            int t_ = grow - b_ * 255;
            arow = t_ * 256 + b_;
        }
        aoff[i] = (unsigned)arow * (unsigned)lda + (unsigned)lk[i];
        boff[i] = (unsigned)(col0 + lr) * (unsigned)ldb + (unsigned)lk[i];
    }

    ull acc2[8][4];
#pragma unroll
    for (int i = 0; i < 8; i++)
#pragma unroll
        for (int j = 0; j < 4; j++) acc2[i][j] = 0ull;

    for (int k0 = 0; k0 < K; k0 += 8) {
#pragma unroll
        for (int i = 0; i < 4; i++) {
            int gk = k0 + lk[i];
            float av = (gk < K) ? A[aoff[i] + k0] : 0.f;
            As2[lk[i]][lrr[i]] = pack2(av, av);
            Bs[lk[i]][lrr[i]] = (gk < K) ? B[boff[i] + k0] : 0.f;
        }
        __syncthreads();
#pragma unroll
        for (int kk = 0; kk < 8; kk++) {
            ull a2[8], b2[4];
            // 4x LDS.128 for duplicated A pairs, 2x LDS.128 for B pairs
            const float4* ap4 = (const float4*)&As2[kk][ty * 8];
            const float4* bp4 = (const float4*)&Bs[kk][tx * 8];
#pragma unroll
            for (int i = 0; i < 4; i++) {
                float4 v = ap4[i];
                a2[2 * i]     = pack2(v.x, v.y);
                a2[2 * i + 1] = pack2(v.z, v.w);
            }
#pragma unroll
            for (int j = 0; j < 2; j++) {
                float4 v = bp4[j];
                b2[2 * j]     = pack2(v.x, v.y);
                b2[2 * j + 1] = pack2(v.z, v.w);
            }
#pragma unroll
            for (int i = 0; i < 8; i++)
#pragma unroll
                for (int j = 0; j < 4; j++) fma2(acc2[i][j], a2[i], b2[j]);
        }
        __syncthreads();
    }

    // unpack to scalar tile
    float acc[8][8];
#pragma unroll
    for (int i = 0; i < 8; i++)
#pragma unroll
        for (int j = 0; j < 4; j++)
            unpack2(acc2[i][j], acc[i][2 * j], acc[i][2 * j + 1]);

    if (MODE == 0) {
        // transposed store: C[t][col][b], 128-row tile = fixed t, b range
        int tt = row0 >> 8;
        int b0 = (row0 & 255) + ty * 8;
#pragma unroll
        for (int j = 0; j < 8; j++) {
            int gcol = col0 + tx * 8 + j;
            float bz = bias[gcol];
            float4 v0 = make_float4(acc[0][j] + bz, acc[1][j] + bz,
                                    acc[2][j] + bz, acc[3][j] + bz);
            float4 v1 = make_float4(acc[4][j] + bz, acc[5][j] + bz,
                                    acc[6][j] + bz, acc[7][j] + bz);
            size_t base = ((size_t)tt * G3H + gcol) * B_DIM + b0;
            *(float4*)(C + base) = v0;
            *(float4*)(C + base + 4) = v1;
        }
        return;
    }

#pragma unroll
    for (int i = 0; i < 8; i++) {
        int grow = row0 + ty * 8 + i;
        float tdv = 0.f;
        int b_ = 0, t_ = 0;
        if (MODE == 1) tdv = td[grow];
        if (MODE == 2) { b_ = grow / 255; t_ = grow - b_ * 255; }
#pragma unroll
        for (int j = 0; j < 8; j++) {
            int gcol = col0 + tx * 8 + j;
            float v = acc[i][j];
            if (MODE == 1) {
                v += bias[gcol] + tdv * w1last[(size_t)gcol * 513];
                v = fsigmoid(v);
            } else { // MODE 2
                v = (t_ < lengths[b_] - 1) ? (v + bias[gcol]) : 0.f;
            }
            C[(size_t)grow * ldc + gcol] = v;
        }
    }
}

// =======================================================================
// Persistent GRU: 128 CTAs resident (1/SM), all 256 steps in one launch.
// =======================================================================
__global__ __launch_bounds__(GTPB, 1)
void gru_persistent(const float* __restrict__ h0,
                    const float* __restrict__ xwT,
                    const float* __restrict__ w_hh,
                    const float* __restrict__ b_hh,
                    const int*   __restrict__ lengths,
                    float* __restrict__ hT,
                    float* __restrict__ hidden,
                    unsigned* __restrict__ bar)
{
    extern __shared__ float sm[];
    float* w_s = sm;                       // [512][48]
    float* h_s = sm + H_DIM * 48;          // [2][64][64]

    const int tid = threadIdx.x;
    const int jc  = blockIdx.x & 31;
    const int bgi = blockIdx.x >> 5;
    const int ubase = jc * UPC;
    const int bbase = bgi * BPC;
    const int ut = tid >> 5;               // 0..7
    const int bt = tid & 31;               // 0..31
    const int u0 = ut * 2;
    const int b0 = bt * 2;

    unsigned sm_base;
    asm("{.reg .u64 t0; cvta.to.shared.u64 t0, %1; cvt.u32.u64 %0, t0;}"
        : "=r"(sm_base) : "l"(sm));
    const unsigned sw_w = sm_base;
    const unsigned sw_h = sm_base + H_DIM * 48 * 4;

    // ---- one-time: load w slice (48 rows x 512) transposed into w_s[k][row]
    for (int i = tid; i < 48 * 128; i += GTPB) {
        int r = i >> 7, kq = i & 127;
        int g = r >> 4, u = r & 15;
        float4 w4 = *(const float4*)(w_hh + (size_t)(g * H_DIM + ubase + u) * H_DIM + kq * 4);
        int col = g * 16 + u;
        w_s[(kq * 4 + 0) * 48 + col] = w4.x;
        w_s[(kq * 4 + 1) * 48 + col] = w4.y;
        w_s[(kq * 4 + 2) * 48 + col] = w4.z;
        w_s[(kq * 4 + 3) * 48 + col] = w4.w;
    }
    // ---- one-time: transpose own tile of h0 into hT[0]
    for (int i = tid; i < UPC * BPC; i += GTPB) {
        int u = i >> 6, b = i & 63;
        hT[(size_t)(ubase + u) * B_DIM + bbase + b] =
            h0[(size_t)(bbase + b) * H_DIM + ubase + u];
    }
    // grid barrier 0
    __syncthreads();
    if (tid == 0) {
        __threadfence();
        atomicAdd(&bar[0], 1u);
        volatile unsigned* f = &bar[0];
        while (*f < (unsigned)NCTA) __nanosleep(64);
    }
    __syncthreads();

    float bh[3][2];
#pragma unroll
    for (int g = 0; g < 3; g++) {
        bh[g][0] = b_hh[g * H_DIM + ubase + u0];
        bh[g][1] = b_hh[g * H_DIM + ubase + u0 + 1];
    }
    const int len0 = lengths[bbase + b0];
    const int len1 = lengths[bbase + b0 + 1];

    const unsigned hoff = b0 * 4;
    const unsigned woff = u0 * 4;

    for (int t = 0; t < T_DIM; t++) {
        const float* hcur = hT + (size_t)(t & 1) * H_DIM * B_DIM;
        float*       hnxt = hT + (size_t)((t + 1) & 1) * H_DIM * B_DIM;

        ull accd0 = 0, accd1 = 0, accd2 = 0;
        ull accc0 = 0, accc1 = 0, accc2 = 0;

        float4 pf[4];
#pragma unroll
        for (int i = 0; i < 4; i++) {
            int q = tid + i * GTPB;
            int k = q >> 4, bq = q & 15;
            pf[i] = __ldcg((const float4*)(hcur + (size_t)k * B_DIM + bbase + bq * 4));
        }

        for (int c = 0; c < NCHUNK; c++) {
            __syncthreads();
#pragma unroll
            for (int i = 0; i < 4; i++) {
                int q = tid + i * GTPB;
                int k = q >> 4, bq = q & 15;
                *(float4*)(h_s + (c & 1) * (CHUNK * BPC) + k * BPC + bq * 4) = pf[i];
            }
            if (c < NCHUNK - 1) {
#pragma unroll
                for (int i = 0; i < 4; i++) {
                    int q = tid + i * GTPB;
                    int k = q >> 4, bq = q & 15;
                    pf[i] = __ldcg((const float4*)(hcur + (size_t)((c + 1) * CHUNK + k) * B_DIM + bbase + bq * 4));
                }
            }
            __syncthreads();

            const unsigned hbase = sw_h + (c & 1) * (CHUNK * BPC * 4) + hoff;
            const unsigned wbase = sw_w + (c * CHUNK) * 192 + woff;
#pragma unroll 32
            for (int kk = 0; kk < CHUNK; kk++) {
                ull h2  = lds64(hbase + kk * 256);
                ull h2s = swap64(h2);
                ull w0  = lds64(wbase + kk * 192);
                ull w1  = lds64(wbase + kk * 192 + 64);
                ull w2  = lds64(wbase + kk * 192 + 128);
                fma2(accd0, w0, h2);  fma2(accc0, w0, h2s);
                fma2(accd1, w1, h2);  fma2(accc1, w1, h2s);
                fma2(accd2, w2, h2);  fma2(accc2, w2, h2s);
            }
        }

        float A0[4], A1[4], A2[4];
        unpack2(accd0, A0[0], A0[3]); unpack2(accc0, A0[1], A0[2]);
        unpack2(accd1, A1[0], A1[3]); unpack2(accc1, A1[1], A1[2]);
        unpack2(accd2, A2[0], A2[3]); unpack2(accc2, A2[1], A2[2]);

#pragma unroll
        for (int cb = 0; cb < 4; cb++) {
            const int du = cb >> 1, db = cb & 1;
            const int uu = ubase + u0 + du;
            const int bb = bbase + b0 + db;
            const size_t xbase = ((size_t)t * G3H + uu) * B_DIM + bb;
            float xr = __ldg(xwT + xbase);
            float xz = __ldg(xwT + xbase + (size_t)H_DIM * B_DIM);
            float xn = __ldg(xwT + xbase + (size_t)2 * H_DIM * B_DIM);
            float hold = __ldcg(hcur + (size_t)uu * B_DIM + bb);
            float r = fsigmoid(xr + A0[cb] + bh[0][du]);
            float z = fsigmoid(xz + A1[cb] + bh[1][du]);
            float n = ftanh(xn + r * (A2[cb] + bh[2][du]));
            float hnew = (1.f - z) * n + z * hold;
            bool valid = t < ((db == 0) ? len0 : len1);
            hnxt[(size_t)uu * B_DIM + bb] = valid ? hnew : hold;
            hidden[((size_t)t * B_DIM + bb) * H_DIM + uu] = valid ? hnew : 0.f;
        }

        __syncthreads();
        if (tid == 0) {
            __threadfence();
            atomicAdd(&bar[t + 1], 1u);
            volatile unsigned* f = &bar[t + 1];
            while (*f < (unsigned)NCTA) __nanosleep(64);
        }
        __syncthreads();
    }
}

// =======================================================================
__global__ void td_kernel(const float* __restrict__ x, float* __restrict__ td)
{
    int i = blockIdx.x * 256 + threadIdx.x;
    if (i < PRE_ROWS) {
        int b = i / 255;
        int t = i - b * 255;
        td[i] = x[(size_t)((t + 1) * B_DIM + b) * (D_DIM + 1)]
              - x[(size_t)(t * B_DIM + b) * (D_DIM + 1)];
    }
}

// =======================================================================
__global__ void tail_kernel(const float* __restrict__ hT0,
                            const float* __restrict__ wp,
                            const float* __restrict__ bp,
                            const int* __restrict__ lengths,
                            float* __restrict__ out)
{
    int b = blockIdx.x;
    int w = threadIdx.x >> 5;
    int lane = threadIdx.x & 31;
    float s = 0.f;
    for (int k = lane; k < H_DIM; k += 32)
        s += hT0[(size_t)k * B_DIM + b] * wp[(size_t)w * H_DIM + k];
#pragma unroll
    for (int o = 16; o; o >>= 1) s += __shfl_xor_sync(0xffffffffu, s, o);
    if (lane == 0)
        out[PRED_ELEMS + b * 3 + w] = expf(-(s + bp[w]));
    if (threadIdx.x == 0)
        out[PRED_ELEMS + B_DIM * 3 + b] = (float)lengths[b];
}

// =======================================================================
extern "C" void kernel_launch(void* const* d_in, const int* in_sizes, int n_in,
                              void* d_out, int out_size)
{
    const float* x    = (const float*)d_in[0];
    const float* h0   = (const float*)d_in[1];
    const int*   lens = (const int*)  d_in[2];
    const float* w_ih = (const float*)d_in[3];
    const float* w_hh = (const float*)d_in[4];
    const float* b_ih = (const float*)d_in[5];
    const float* b_hh = (const float*)d_in[6];
    const float* w1   = (const float*)d_in[7];
    const float* b1   = (const float*)d_in[8];
    const float* w2   = (const float*)d_in[9];
    const float* b2   = (const float*)d_in[10];
    const float* wp   = (const float*)d_in[11];
    const float* bp   = (const float*)d_in[12];
    float* out = (float*)d_out;

    float *xwT, *hidden, *pre, *td, *hT;
    unsigned* bar;
    cudaGetSymbolAddress((void**)&xwT,    g_xwT);
    cudaGetSymbolAddress((void**)&hidden, g_hidden);
    cudaGetSymbolAddress((void**)&pre,    g_pre);
    cudaGetSymbolAddress((void**)&td,     g_td);
    cudaGetSymbolAddress((void**)&hT,     g_hT);
    cudaGetSymbolAddress((void**)&bar,    g_bar);

    cudaFuncSetAttribute(gru_persistent,
                         cudaFuncAttributeMaxDynamicSharedMemorySize, GRU_SMEM);

    cudaMemsetAsync(bar, 0, 260 * sizeof(unsigned));

    td_kernel<<<255, 256>>>(x, td);

    // xwT[t][col][b] = (x @ w_ih^T + b_ih) transposed
    gemm128<0><<<dim3(G3H / 128, (T_DIM * B_DIM) / 128), 256>>>(
        x, w_ih, xwT, T_DIM * B_DIM, G3H, D_DIM + 1,
        D_DIM + 1, D_DIM + 1, G3H, b_ih, nullptr, nullptr, nullptr);

    // persistent GRU (all 256 steps)
    gru_persistent<<<NCTA, GTPB, GRU_SMEM>>>(h0, xwT, w_hh, b_hh, lens,
                                             hT, hidden, bar);

    // pre = sigmoid(hwt[:, :-1] @ w1^T + b1), td column fused
    gemm128<1><<<dim3(K10D / 128, PRE_ROWS / 128), 256>>>(
        hidden, w1, pre, PRE_ROWS, K10D, H_DIM,
        H_DIM, H_DIM + 1, K10D, b1, td, w1 + H_DIM, nullptr);

    // preds = mask(pre @ w2^T + b2) -> d_out
    gemm128<2><<<dim3(1, PRE_ROWS / 128), 256>>>(
        pre, w2, out, PRE_ROWS, D_DIM, K10D,
        K10D, K10D, D_DIM, b2, nullptr, nullptr, lens);

    // dist_params + lengths (final h is hT buffer 0 after 256 steps)
    tail_kernel<<<B_DIM, 96>>>(hT, wp, bp, lens, out);
}

// round 12
// speedup vs baseline: 1.6003x; 1.4152x over previous
#include <cuda_runtime.h>
#include <cuda_bf16.h>
#include <mma.h>
#include <math.h>
#include <stdint.h>

using namespace nvcuda;

// ---------------- problem constants ----------------
#define T_DIM 256
#define B_DIM 256
#define D_DIM 128
#define H_DIM 512
#define G3H   1536            // 3*H
#define TM1   255             // T-1
#define K10D  1280            // 10*D
#define PRE_ROWS (B_DIM*TM1)  // 65280
#define PRED_ELEMS (PRE_ROWS*D_DIM)  // 8355840
#define KXP   192             // padded K for x / w_ih (129 -> 192)

// WMMA GEMM geometry
#define BK     32
#define LDSO   48             // operand smem pitch (bf16 elements, 96B)
#define EPAD   132            // epilogue smem pitch (floats)
#define GEMM_SMEM (128*EPAD*4)   // 67584 B (operands fit in first 48KB)

// persistent GRU geometry
#define NCTA   128
#define GTPB   256
#define UPC    16
#define BPC    64
#define CHUNK  64
#define NCHUNK (H_DIM/CHUNK)
#define GRU_SMEM ((H_DIM*48 + 2*CHUNK*BPC)*4)   // 131072 B

// ---------------- scratch (static device arrays) ----------------
__device__ float g_xwT[(size_t)T_DIM * G3H * B_DIM];      // [t][col][b] fp32
__device__ float g_hidden[(size_t)T_DIM * B_DIM * H_DIM]; // [t][b][H]   fp32
__device__ float g_td[PRE_ROWS];
__device__ float g_hT[2 * H_DIM * B_DIM];
__device__ unsigned g_bar[260];

// bf16 split operands
__device__ __nv_bfloat16 g_Axhi[(size_t)T_DIM * B_DIM * KXP];
__device__ __nv_bfloat16 g_Axlo[(size_t)T_DIM * B_DIM * KXP];
__device__ __nv_bfloat16 g_Bwihhi[(size_t)G3H * KXP];
__device__ __nv_bfloat16 g_Bwihlo[(size_t)G3H * KXP];
__device__ __nv_bfloat16 g_Ahidhi[(size_t)PRE_ROWS * H_DIM];
__device__ __nv_bfloat16 g_Ahidlo[(size_t)PRE_ROWS * H_DIM];
__device__ __nv_bfloat16 g_Bw1hi[(size_t)K10D * H_DIM];
__device__ __nv_bfloat16 g_Bw1lo[(size_t)K10D * H_DIM];
__device__ __nv_bfloat16 g_Bw2hi[(size_t)D_DIM * K10D];
__device__ __nv_bfloat16 g_Bw2lo[(size_t)D_DIM * K10D];
__device__ __nv_bfloat16 g_Phi[(size_t)PRE_ROWS * K10D];
__device__ __nv_bfloat16 g_Plo[(size_t)PRE_ROWS * K10D];

// ---------------- generic helpers ----------------
typedef unsigned long long ull;
__device__ __forceinline__ ull lds64(unsigned a) {
    ull v; asm("ld.shared.b64 %0, [%1];" : "=l"(v) : "r"(a)); return v;
}
__device__ __forceinline__ ull swap64(ull p) {
    unsigned lo, hi;
    asm("mov.b64 {%0,%1}, %2;" : "=r"(lo), "=r"(hi) : "l"(p));
    ull q; asm("mov.b64 %0, {%1,%2};" : "=l"(q) : "r"(hi), "r"(lo)); return q;
}
__device__ __forceinline__ void fma2(ull& acc, ull a, ull b) {
    asm("fma.rn.f32x2 %0, %1, %2, %0;" : "+l"(acc) : "l"(a), "l"(b));
}
__device__ __forceinline__ void unpack2(ull p, float& lo, float& hi) {
    asm("mov.b64 {%0,%1}, %2;" : "=f"(lo), "=f"(hi) : "l"(p));
}
__device__ __forceinline__ float fsigmoid(float x) {
    return __fdividef(1.f, 1.f + __expf(-x));
}
__device__ __forceinline__ float ftanh(float x) {
    return 1.f - __fdividef(2.f, __expf(2.f * x) + 1.f);
}
__device__ __forceinline__ uint32_t s2u(const void* p) {
    uint32_t a;
    asm("{ .reg .u64 t; cvta.to.shared.u64 t, %1; cvt.u32.u64 %0, t; }"
        : "=r"(a) : "l"(p));
    return a;
}

// =======================================================================
// WMMA split-bf16 GEMM: C[M,N] = A[M,K] * B[N,K]^T  (fp32 accumulate)
// acc += Ahi*Bhi + Alo*Bhi + Ahi*Blo   (lo*lo dropped, err ~2^-16)
// CTA tile 128x128, 8 warps (4M x 2N), warp tile 32x64, BK=32.
// MODE 0: xw    -> C[t][col][b] transposed store, + bias
// MODE 1: pre   -> sigmoid(c + td[row]*w1[col*513+512] + bias) -> Phi/Plo
// MODE 2: preds -> c = (t < len[b]-1) ? c+bias : 0  -> C row-major
// =======================================================================
template <int MODE>
__global__ __launch_bounds__(256)
void wgemm(const __nv_bfloat16* __restrict__ Ahi, const __nv_bfloat16* __restrict__ Alo,
           const __nv_bfloat16* __restrict__ Bhi, const __nv_bfloat16* __restrict__ Blo,
           float* __restrict__ C, int K, int lda, int ldb,
           const float* __restrict__ bias, const float* __restrict__ tdv,
           const float* __restrict__ w1f, const int* __restrict__ lengths,
           __nv_bfloat16* __restrict__ Phi, __nv_bfloat16* __restrict__ Plo)
{
    extern __shared__ __align__(16) char smem[];
    __nv_bfloat16* sAhi = (__nv_bfloat16*)smem;            // [128][48]
    __nv_bfloat16* sAlo = sAhi + 128 * LDSO;
    __nv_bfloat16* sBhi = sAlo + 128 * LDSO;
    __nv_bfloat16* sBlo = sBhi + 128 * LDSO;
    float* esm = (float*)smem;                             // [128][132] epilogue

    const int tid = threadIdx.x;
    const int wid = tid >> 5;
    const int lane = tid & 31;
    const int row0 = blockIdx.y * 128;
    const int col0 = blockIdx.x * 128;
    const int wm = (wid & 3) * 32;     // warp row offset in tile
    const int wn = (wid >> 2) * 64;    // warp col offset in tile

    wmma::fragment<wmma::accumulator, 16, 16, 16, float> acc[2][4];
#pragma unroll
    for (int i = 0; i < 2; i++)
#pragma unroll
        for (int j = 0; j < 4; j++) wmma::fill_fragment(acc[i][j], 0.f);

    // global load mapping: 256 threads cover 128 rows x 32 k in TWO row
    // halves per operand: thread handles rows lr and lr+64, one uint4 each.
    const int lr = tid >> 2, lq = tid & 3;
    const __nv_bfloat16* gAhi0 = Ahi + (size_t)(row0 + lr) * lda + lq * 8;
    const __nv_bfloat16* gAhi1 = gAhi0 + (size_t)64 * lda;
    const __nv_bfloat16* gAlo0 = Alo + (size_t)(row0 + lr) * lda + lq * 8;
    const __nv_bfloat16* gAlo1 = gAlo0 + (size_t)64 * lda;
    const __nv_bfloat16* gBhi0 = Bhi + (size_t)(col0 + lr) * ldb + lq * 8;
    const __nv_bfloat16* gBhi1 = gBhi0 + (size_t)64 * ldb;
    const __nv_bfloat16* gBlo0 = Blo + (size_t)(col0 + lr) * ldb + lq * 8;
    const __nv_bfloat16* gBlo1 = gBlo0 + (size_t)64 * ldb;
    const int soff0 = lr * LDSO + lq * 8;
    const int soff1 = (lr + 64) * LDSO + lq * 8;

#pragma unroll 1
    for (int kc = 0; kc < K; kc += BK) {
        __syncthreads();
        *(uint4*)(sAhi + soff0) = *(const uint4*)(gAhi0 + kc);
        *(uint4*)(sAhi + soff1) = *(const uint4*)(gAhi1 + kc);
        *(uint4*)(sAlo + soff0) = *(const uint4*)(gAlo0 + kc);
        *(uint4*)(sAlo + soff1) = *(const uint4*)(gAlo1 + kc);
        *(uint4*)(sBhi + soff0) = *(const uint4*)(gBhi0 + kc);
        *(uint4*)(sBhi + soff1) = *(const uint4*)(gBhi1 + kc);
        *(uint4*)(sBlo + soff0) = *(const uint4*)(gBlo0 + kc);
        *(uint4*)(sBlo + soff1) = *(const uint4*)(gBlo1 + kc);
        __syncthreads();

#pragma unroll
        for (int ks = 0; ks < BK; ks += 16) {
            wmma::fragment<wmma::matrix_a, 16, 16, 16, __nv_bfloat16, wmma::row_major> ahi[2], alo[2];
#pragma unroll
            for (int i = 0; i < 2; i++) {
                wmma::load_matrix_sync(ahi[i], sAhi + (wm + 16 * i) * LDSO + ks, LDSO);
                wmma::load_matrix_sync(alo[i], sAlo + (wm + 16 * i) * LDSO + ks, LDSO);
            }
#pragma unroll
            for (int j = 0; j < 4; j++) {
                wmma::fragment<wmma::matrix_b, 16, 16, 16, __nv_bfloat16, wmma::col_major> bhi, blo;
                wmma::load_matrix_sync(bhi, sBhi + (wn + 16 * j) * LDSO + ks, LDSO);
                wmma::load_matrix_sync(blo, sBlo + (wn + 16 * j) * LDSO + ks, LDSO);
#pragma unroll
                for (int i = 0; i < 2; i++) {
                    wmma::mma_sync(acc[i][j], ahi[i], bhi, acc[i][j]);
                    wmma::mma_sync(acc[i][j], alo[i], bhi, acc[i][j]);
                    wmma::mma_sync(acc[i][j], ahi[i], blo, acc[i][j]);
                }
            }
        }
    }

    // stage C tile to smem
    __syncthreads();
#pragma unroll
    for (int i = 0; i < 2; i++)
#pragma unroll
        for (int j = 0; j < 4; j++)
            wmma::store_matrix_sync(esm + (wm + 16 * i) * EPAD + wn + 16 * j,
                                    acc[i][j], EPAD, wmma::mem_row_major);
    __syncthreads();

    // ---------------- epilogues ----------------
    if (MODE == 0) {
        // transposed store: tile rows are (t fixed, b = row0&255 .. +127)
        const int tt = row0 >> 8;
        const int bb0 = row0 & 255;
#pragma unroll 1
        for (int cc = wid; cc < 128; cc += 8) {
            const int col = col0 + cc;
            const float bz = bias[col];
            float* dst = C + ((size_t)tt * G3H + col) * B_DIM + bb0;
#pragma unroll
            for (int rr = lane; rr < 128; rr += 32)
                dst[rr] = esm[rr * EPAD + cc] + bz;
        }
    } else if (MODE == 1) {
        const int r = tid >> 1, h = tid & 1;
        const int grow = row0 + r;
        const float tdval = tdv[grow];
        const float* esrow = esm + r * EPAD + h * 64;
        const size_t obase = (size_t)grow * K10D + col0 + h * 64;
#pragma unroll
        for (int g = 0; g < 2; g++) {
            uint32_t hp[16], lp[16];
#pragma unroll
            for (int q = 0; q < 16; q++) {
                const int c0 = g * 32 + q * 2;
                const int col = col0 + h * 64 + c0;
                float v0 = esrow[c0]     + bias[col]
                         + tdval * w1f[(size_t)col * 513 + 512];
                float v1 = esrow[c0 + 1] + bias[col + 1]
                         + tdval * w1f[(size_t)(col + 1) * 513 + 512];
                float s0 = fsigmoid(v0);
                float s1 = fsigmoid(v1);
                __nv_bfloat16 h0 = __float2bfloat16(s0);
                __nv_bfloat16 h1 = __float2bfloat16(s1);
                __nv_bfloat16 l0 = __float2bfloat16(s0 - __bfloat162float(h0));
                __nv_bfloat16 l1 = __float2bfloat16(s1 - __bfloat162float(h1));
                __nv_bfloat162 hh = __halves2bfloat162(h0, h1);
                __nv_bfloat162 ll = __halves2bfloat162(l0, l1);
                hp[q] = *(uint32_t*)&hh;
                lp[q] = *(uint32_t*)&ll;
            }
#pragma unroll
            for (int q = 0; q < 4; q++) {
                *(uint4*)(Phi + obase + g * 32 + q * 8) = ((uint4*)hp)[q];
                *(uint4*)(Plo + obase + g * 32 + q * 8) = ((uint4*)lp)[q];
            }
        }
    } else { // MODE 2
        const int r = tid >> 1, h = tid & 1;
        const int grow = row0 + r;
        const int b_ = grow / 255;
        const int t_ = grow - b_ * 255;
        const bool valid = t_ < lengths[b_] - 1;
        const float* esrow = esm + r * EPAD + h * 64;
        float* dst = C + (size_t)grow * D_DIM + col0 + h * 64;
#pragma unroll
        for (int q = 0; q < 16; q++) {
            const int c0 = q * 4;
            const int col = col0 + h * 64 + c0;
            float4 v;
            v.x = valid ? (esrow[c0]     + bias[col])     : 0.f;
            v.y = valid ? (esrow[c0 + 1] + bias[col + 1]) : 0.f;
            v.z = valid ? (esrow[c0 + 2] + bias[col + 2]) : 0.f;
            v.w = valid ? (esrow[c0 + 3] + bias[col + 3]) : 0.f;
            *(float4*)(dst + c0) = v;
        }
    }
}

// =======================================================================
// conversions: fp32 -> bf16 hi/lo with zero-padding
// =======================================================================
__global__ void conv_pad(const float* __restrict__ src,
                         __nv_bfloat16* __restrict__ hi,
                         __nv_bfloat16* __restrict__ lo,
                         int rows, int sld, int dld, int valid)
{
    int i = blockIdx.x * 256 + threadIdx.x;
    if (i >= rows * dld) return;
    int r = i / dld, c = i - r * dld;
    float v = (c < valid) ? src[(size_t)r * sld + c] : 0.f;
    __nv_bfloat16 h = __float2bfloat16(v);
    hi[i] = h;
    lo[i] = __float2bfloat16(v - __bfloat162float(h));
}

// hidden [t][b][H] fp32 -> Ahid [(b*255+t)][H] bf16 hi/lo  (t < 255)
__global__ void conv_hidden(const float* __restrict__ hid,
                            __nv_bfloat16* __restrict__ hi,
                            __nv_bfloat16* __restrict__ lo)
{
    int i = blockIdx.x * 256 + threadIdx.x;
    if (i >= PRE_ROWS * H_DIM) return;
    int r = i >> 9, c = i & 511;
    int b = r / 255, t = r - b * 255;
    float v = hid[((size_t)t * B_DIM + b) * H_DIM + c];
    __nv_bfloat16 h = __float2bfloat16(v);
    hi[i] = h;
    lo[i] = __float2bfloat16(v - __bfloat162float(h));
}

// =======================================================================
// Persistent GRU: 128 CTAs resident (1/SM), all 256 steps in one launch.
// =======================================================================
__global__ __launch_bounds__(GTPB, 1)
void gru_persistent(const float* __restrict__ h0,
                    const float* __restrict__ xwT,
                    const float* __restrict__ w_hh,
                    const float* __restrict__ b_hh,
                    const int*   __restrict__ lengths,
                    float* __restrict__ hT,
                    float* __restrict__ hidden,
                    unsigned* __restrict__ bar)
{
    extern __shared__ float sm[];
    float* w_s = sm;                       // [512][48]
    float* h_s = sm + H_DIM * 48;          // [2][64][64]

    const int tid = threadIdx.x;
    const int jc  = blockIdx.x & 31;
    const int bgi = blockIdx.x >> 5;
    const int ubase = jc * UPC;
    const int bbase = bgi * BPC;
    const int ut = tid >> 5;
    const int bt = tid & 31;
    const int u0 = ut * 2;
    const int b0 = bt * 2;

    unsigned sm_base = s2u(sm);
    const unsigned sw_w = sm_base;
    const unsigned sw_h = sm_base + H_DIM * 48 * 4;

    for (int i = tid; i < 48 * 128; i += GTPB) {
        int r = i >> 7, kq = i & 127;
        int g = r >> 4, u = r & 15;
        float4 w4 = *(const float4*)(w_hh + (size_t)(g * H_DIM + ubase + u) * H_DIM + kq * 4);
        int col = g * 16 + u;
        w_s[(kq * 4 + 0) * 48 + col] = w4.x;
        w_s[(kq * 4 + 1) * 48 + col] = w4.y;
        w_s[(kq * 4 + 2) * 48 + col] = w4.z;
        w_s[(kq * 4 + 3) * 48 + col] = w4.w;
    }
    for (int i = tid; i < UPC * BPC; i += GTPB) {
        int u = i >> 6, b = i & 63;
        hT[(size_t)(ubase + u) * B_DIM + bbase + b] =
            h0[(size_t)(bbase + b) * H_DIM + ubase + u];
    }
    __syncthreads();
    if (tid == 0) {
        __threadfence();
        atomicAdd(&bar[0], 1u);
        volatile unsigned* f = &bar[0];
        while (*f < (unsigned)NCTA) __nanosleep(64);
    }
    __syncthreads();

    float bh[3][2];
#pragma unroll
    for (int g = 0; g < 3; g++) {
        bh[g][0] = b_hh[g * H_DIM + ubase + u0];
        bh[g][1] = b_hh[g * H_DIM + ubase + u0 + 1];
    }
    const int len0 = lengths[bbase + b0];
    const int len1 = lengths[bbase + b0 + 1];

    const unsigned hoff = b0 * 4;
    const unsigned woff = u0 * 4;

    for (int t = 0; t < T_DIM; t++) {
        const float* hcur = hT + (size_t)(t & 1) * H_DIM * B_DIM;
        float*       hnxt = hT + (size_t)((t + 1) & 1) * H_DIM * B_DIM;

        ull accd0 = 0, accd1 = 0, accd2 = 0;
        ull accc0 = 0, accc1 = 0, accc2 = 0;

        float4 pf[4];
#pragma unroll
        for (int i = 0; i < 4; i++) {
            int q = tid + i * GTPB;
            int k = q >> 4, bq = q & 15;
            pf[i] = __ldcg((const float4*)(hcur + (size_t)k * B_DIM + bbase + bq * 4));
        }

        for (int c = 0; c < NCHUNK; c++) {
            __syncthreads();
#pragma unroll
            for (int i = 0; i < 4; i++) {
                int q = tid + i * GTPB;
                int k = q >> 4, bq = q & 15;
                *(float4*)(h_s + (c & 1) * (CHUNK * BPC) + k * BPC + bq * 4) = pf[i];
            }
            if (c < NCHUNK - 1) {
#pragma unroll
                for (int i = 0; i < 4; i++) {
                    int q = tid + i * GTPB;
                    int k = q >> 4, bq = q & 15;
                    pf[i] = __ldcg((const float4*)(hcur + (size_t)((c + 1) * CHUNK + k) * B_DIM + bbase + bq * 4));
                }
            }
            __syncthreads();

            const unsigned hbase = sw_h + (c & 1) * (CHUNK * BPC * 4) + hoff;
            const unsigned wbase = sw_w + (c * CHUNK) * 192 + woff;
#pragma unroll 32
            for (int kk = 0; kk < CHUNK; kk++) {
                ull h2  = lds64(hbase + kk * 256);
                ull h2s = swap64(h2);
                ull w0  = lds64(wbase + kk * 192);
                ull w1v = lds64(wbase + kk * 192 + 64);
                ull w2v = lds64(wbase + kk * 192 + 128);
                fma2(accd0, w0, h2);   fma2(accc0, w0, h2s);
                fma2(accd1, w1v, h2);  fma2(accc1, w1v, h2s);
                fma2(accd2, w2v, h2);  fma2(accc2, w2v, h2s);
            }
        }

        float A0[4], A1[4], A2[4];
        unpack2(accd0, A0[0], A0[3]); unpack2(accc0, A0[1], A0[2]);
        unpack2(accd1, A1[0], A1[3]); unpack2(accc1, A1[1], A1[2]);
        unpack2(accd2, A2[0], A2[3]); unpack2(accc2, A2[1], A2[2]);

#pragma unroll
        for (int cb = 0; cb < 4; cb++) {
            const int du = cb >> 1, db = cb & 1;
            const int uu = ubase + u0 + du;
            const int bb = bbase + b0 + db;
            const size_t xbase = ((size_t)t * G3H + uu) * B_DIM + bb;
            float xr = __ldg(xwT + xbase);
            float xz = __ldg(xwT + xbase + (size_t)H_DIM * B_DIM);
            float xn = __ldg(xwT + xbase + (size_t)2 * H_DIM * B_DIM);
            float hold = __ldcg(hcur + (size_t)uu * B_DIM + bb);
            float r = fsigmoid(xr + A0[cb] + bh[0][du]);
            float z = fsigmoid(xz + A1[cb] + bh[1][du]);
            float n = ftanh(xn + r * (A2[cb] + bh[2][du]));
            float hnew = (1.f - z) * n + z * hold;
            bool valid = t < ((db == 0) ? len0 : len1);
            hnxt[(size_t)uu * B_DIM + bb] = valid ? hnew : hold;
            hidden[((size_t)t * B_DIM + bb) * H_DIM + uu] = valid ? hnew : 0.f;
        }

        __syncthreads();
        if (tid == 0) {
            __threadfence();
            atomicAdd(&bar[t + 1], 1u);
            volatile unsigned* f = &bar[t + 1];
            while (*f < (unsigned)NCTA) __nanosleep(64);
        }
        __syncthreads();
    }
}

// =======================================================================
__global__ void td_kernel(const float* __restrict__ x, float* __restrict__ td)
{
    int i = blockIdx.x * 256 + threadIdx.x;
    if (i < PRE_ROWS) {
        int b = i / 255;
        int t = i - b * 255;
        td[i] = x[(size_t)((t + 1) * B_DIM + b) * (D_DIM + 1)]
              - x[(size_t)(t * B_DIM + b) * (D_DIM + 1)];
    }
}

// =======================================================================
__global__ void tail_kernel(const float* __restrict__ hT0,
                            const float* __restrict__ wp,
                            const float* __restrict__ bp,
                            const int* __restrict__ lengths,
                            float* __restrict__ out)
{
    int b = blockIdx.x;
    int w = threadIdx.x >> 5;
    int lane = threadIdx.x & 31;
    float s = 0.f;
    for (int k = lane; k < H_DIM; k += 32)
        s += hT0[(size_t)k * B_DIM + b] * wp[(size_t)w * H_DIM + k];
#pragma unroll
    for (int o = 16; o; o >>= 1) s += __shfl_xor_sync(0xffffffffu, s, o);
    if (lane == 0)
        out[PRED_ELEMS + b * 3 + w] = expf(-(s + bp[w]));
    if (threadIdx.x == 0)
        out[PRED_ELEMS + B_DIM * 3 + b] = (float)lengths[b];
}

// =======================================================================
extern "C" void kernel_launch(void* const* d_in, const int* in_sizes, int n_in,
                              void* d_out, int out_size)
{
    const float* x    = (const float*)d_in[0];
    const float* h0   = (const float*)d_in[1];
    const int*   lens = (const int*)  d_in[2];
    const float* w_ih = (const float*)d_in[3];
    const float* w_hh = (const float*)d_in[4];
    const float* b_ih = (const float*)d_in[5];
    const float* b_hh = (const float*)d_in[6];
    const float* w1   = (const float*)d_in[7];
    const float* b1   = (const float*)d_in[8];
    const float* w2   = (const float*)d_in[9];
    const float* b2   = (const float*)d_in[10];
    const float* wp   = (const float*)d_in[11];
    const float* bp   = (const float*)d_in[12];
    float* out = (float*)d_out;

    float *xwT, *hidden, *td, *hT;
    unsigned* bar;
    __nv_bfloat16 *Axhi, *Axlo, *Bwihhi, *Bwihlo, *Ahidhi, *Ahidlo;
    __nv_bfloat16 *Bw1hi, *Bw1lo, *Bw2hi, *Bw2lo, *Phi, *Plo;
    cudaGetSymbolAddress((void**)&xwT,    g_xwT);
    cudaGetSymbolAddress((void**)&hidden, g_hidden);
    cudaGetSymbolAddress((void**)&td,     g_td);
    cudaGetSymbolAddress((void**)&hT,     g_hT);
    cudaGetSymbolAddress((void**)&bar,    g_bar);
    cudaGetSymbolAddress((void**)&Axhi,   g_Axhi);
    cudaGetSymbolAddress((void**)&Axlo,   g_Axlo);
    cudaGetSymbolAddress((void**)&Bwihhi, g_Bwihhi);
    cudaGetSymbolAddress((void**)&Bwihlo, g_Bwihlo);
    cudaGetSymbolAddress((void**)&Ahidhi, g_Ahidhi);
    cudaGetSymbolAddress((void**)&Ahidlo, g_Ahidlo);
    cudaGetSymbolAddress((void**)&Bw1hi,  g_Bw1hi);
    cudaGetSymbolAddress((void**)&Bw1lo,  g_Bw1lo);
    cudaGetSymbolAddress((void**)&Bw2hi,  g_Bw2hi);
    cudaGetSymbolAddress((void**)&Bw2lo,  g_Bw2lo);
    cudaGetSymbolAddress((void**)&Phi,    g_Phi);
    cudaGetSymbolAddress((void**)&Plo,    g_Plo);

    cudaFuncSetAttribute(gru_persistent,
                         cudaFuncAttributeMaxDynamicSharedMemorySize, GRU_SMEM);
    cudaFuncSetAttribute(wgemm<0>,
                         cudaFuncAttributeMaxDynamicSharedMemorySize, GEMM_SMEM);
    cudaFuncSetAttribute(wgemm<1>,
                         cudaFuncAttributeMaxDynamicSharedMemorySize, GEMM_SMEM);
    cudaFuncSetAttribute(wgemm<2>,
                         cudaFuncAttributeMaxDynamicSharedMemorySize, GEMM_SMEM);

    cudaMemsetAsync(bar, 0, 260 * sizeof(unsigned));

    td_kernel<<<255, 256>>>(x, td);

    // conversions for gemm0 operands
    conv_pad<<<(T_DIM * B_DIM * KXP + 255) / 256, 256>>>(
        x, Axhi, Axlo, T_DIM * B_DIM, D_DIM + 1, KXP, D_DIM + 1);
    conv_pad<<<(G3H * KXP + 255) / 256, 256>>>(
        w_ih, Bwihhi, Bwihlo, G3H, D_DIM + 1, KXP, D_DIM + 1);
    // weights for later gemms (independent)
    conv_pad<<<(K10D * H_DIM + 255) / 256, 256>>>(
        w1, Bw1hi, Bw1lo, K10D, H_DIM + 1, H_DIM, H_DIM);
    conv_pad<<<(D_DIM * K10D + 255) / 256, 256>>>(
        w2, Bw2hi, Bw2lo, D_DIM, K10D, K10D, K10D);

    // xwT = (x @ w_ih^T + b_ih) transposed -> [t][col][b]
    wgemm<0><<<dim3(G3H / 128, (T_DIM * B_DIM) / 128), 256, GEMM_SMEM>>>(
        Axhi, Axlo, Bwihhi, Bwihlo, xwT, KXP, KXP, KXP,
        b_ih, nullptr, nullptr, nullptr, nullptr, nullptr);

    // persistent GRU (all 256 steps)
    gru_persistent<<<NCTA, GTPB, GRU_SMEM>>>(h0, xwT, w_hh, b_hh, lens,
                                             hT, hidden, bar);

    // hidden -> bf16 hi/lo in (b,t) row order
    conv_hidden<<<(PRE_ROWS * H_DIM + 255) / 256, 256>>>(hidden, Ahidhi, Ahidlo);

    // pre = sigmoid(hwt[:, :-1] @ w1^T + b1) -> Phi/Plo (bf16 split)
    wgemm<1><<<dim3(K10D / 128, PRE_ROWS / 128), 256, GEMM_SMEM>>>(
        Ahidhi, Ahidlo, Bw1hi, Bw1lo, nullptr, H_DIM, H_DIM, H_DIM,
        b1, td, w1, nullptr, Phi, Plo);

    // preds = mask(pre @ w2^T + b2) -> d_out
    wgemm<2><<<dim3(1, PRE_ROWS / 128), 256, GEMM_SMEM>>>(
        Phi, Plo, Bw2hi, Bw2lo, out, K10D, K10D, K10D,
        b2, nullptr, nullptr, lens, nullptr, nullptr);

    // dist_params + lengths (final h is hT buffer 0 after 256 steps)
    tail_kernel<<<B_DIM, 96>>>(hT, wp, bp, lens, out);
}